// round 15
// baseline (speedup 1.0000x reference)
#include <cuda_runtime.h>

// ============================================================================
// Hand_Input_Sorter — FINAL kernel (converged optimum, session rounds 1-14).
//
// Task: per-frame conditional 65<->65 half-swap of [B*S, 130] fp32, where the
// skip predicate depends on frame elems 0 (h0), 1 (p0), 65 (h1), 66 (p1).
// The swap_pattern input (d_in[1]) is the fixed half-swap permutation and is
// computed analytically rather than gathered.
//
// Measured-optimal configuration:
//   - one-shot grid, 2 adjacent frames per warp, 256-thread blocks
//     (persistent grid-stride: -9%; 512 threads: marginal loss)
//   - front-batched float2 loads (frame base f*130 is even -> 8B aligned),
//     DEFAULT cache policy on loads AND stores (.cs hints measured slower:
//     the 520B-stride frames share straddled 128B-line sectors between
//     neighbor warps, so L2 reuse/write-merge matters)
//   - aligned float2 stores on BOTH paths; the +-65-element swap permutation
//     is realized in registers with warp shuffles (misaligned scattered
//     stores: slower; full float4 alignment via shuffle chains: -13%;
//     smem staging: -32%, ALU-bound)
//   - predicate evaluated lane-locally (h0,p0,h1 already live on lane 0;
//     only p1 shuffled in) with a single boolean broadcast
//
// Measured: device 36.4-37.1us over 4 samples = 272.6 MB / 36.4us
// ~ 7.5 TB/s effective unique-byte throughput ~ 94% of HBM3e spec.
// ============================================================================

static constexpr int FRAME_LEN = 130;
static constexpr unsigned FULL = 0xFFFFFFFFu;

__device__ __forceinline__ bool compute_skip(float h0, float p0, float h1, float p1)
{
    bool nan0 = isnan(h0);
    bool nan1 = isnan(h1);
    bool skip = (h1 > h0);                 // false if either NaN (IEEE, matches jnp)
    skip |= (nan0 && nan1);                // both missing
    skip |= (nan0 && (h1 == 1.0f));        // only hand1, labeled right
    skip |= (nan1 && (h0 == 0.0f));        // only hand0, labeled left
    if (!nan0 && !nan1 && (h0 == h1)) {
        skip |= ((h0 == 0.0f) && (p0 > p1));
        skip |= ((h0 == 1.0f) && (p0 < p1));
    }
    return skip;
}

// Lane-local predicate + single broadcast: h0=a.x, p0=a.y, h1=b.y are lane 0's
// own registers; p1=b.x@1 is shuffled in. Every lane evaluates compute_skip on
// its local values (garbage off lane 0); only lane 0's result is broadcast.
__device__ __forceinline__ bool frame_skip(float2 a, float2 b)
{
    float p1 = __shfl_sync(FULL, b.x, 1);
    bool local = compute_skip(a.x, a.y, b.y, p1);
    return (bool)__shfl_sync(FULL, (int)local, 0);
}

// Pairs: a = pair[lane] (elems 2l,2l+1), b = pair[lane+32] (elems 64+2l,65+2l),
// c = pair[64] (elems 128,129), loaded uniformly on all lanes.
__device__ __forceinline__ void store_frame(float* __restrict__ o, int lane,
                                            float2 a, float2 b, float2 c, bool skip)
{
    float2* __restrict__ o2 = (float2*)o;
    if (skip) {
        o2[lane]      = a;
        o2[lane + 32] = b;
        if (lane == 0) o2[64] = c;
    } else {
        // out[j] = X[j+65] (j<65) / X[j-65] (j>=65), as float2 slots:
        // slot lane:    {b.y, b[lane+1].x} with b[32] := c
        float bx_next = __shfl_down_sync(FULL, b.x, 1);
        float2 v0 = make_float2(b.y, (lane == 31) ? c.x : bx_next);
        // slot lane+32: lane0 -> {c.y, a[0].x}; else {a[lane-1].y, a.x}
        float ay_prev = __shfl_up_sync(FULL, a.y, 1);
        float a0x     = __shfl_sync(FULL, a.x, 0);
        float2 v1 = (lane == 0) ? make_float2(c.y, a0x)
                                : make_float2(ay_prev, a.x);
        // slot 64: {a[31].y, b[0].x}
        float ay31 = __shfl_sync(FULL, a.y, 31);
        float b0x  = __shfl_sync(FULL, b.x, 0);
        o2[lane]      = v0;
        o2[lane + 32] = v1;
        if (lane == 0) o2[64] = make_float2(ay31, b0x);
    }
}

__global__ __launch_bounds__(256) void hand_sorter_final(
    const float* __restrict__ X,
    float* __restrict__ out,
    int n_frames)
{
    const int gw   = blockIdx.x * (blockDim.x >> 5) + (threadIdx.x >> 5);
    const int lane = threadIdx.x & 31;
    const int f0   = gw * 2;
    if (f0 >= n_frames) return;
    const bool has2 = (f0 + 1) < n_frames;

    const float2* __restrict__ i0 = (const float2*)(X + (size_t)f0 * FRAME_LEN);
    const float2* __restrict__ i1 = (const float2*)(X + (size_t)(f0 + 1) * FRAME_LEN);

    // Front-batch all loads; default cache policy.
    float2 a0 = __ldg(&i0[lane]);
    float2 b0 = __ldg(&i0[lane + 32]);
    float2 c0 = __ldg(&i0[64]);
    float2 a1 = make_float2(0.f, 0.f), b1 = a1, c1 = a1;
    if (has2) {
        a1 = __ldg(&i1[lane]);
        b1 = __ldg(&i1[lane + 32]);
        c1 = __ldg(&i1[64]);
    }

    bool skip0 = frame_skip(a0, b0);
    bool skip1 = has2 ? frame_skip(a1, b1) : false;

    store_frame(out + (size_t)f0 * FRAME_LEN, lane, a0, b0, c0, skip0);
    if (has2)
        store_frame(out + (size_t)(f0 + 1) * FRAME_LEN, lane, a1, b1, c1, skip1);
}

extern "C" void kernel_launch(void* const* d_in, const int* in_sizes, int n_in,
                              void* d_out, int out_size)
{
    const float* X = (const float*)d_in[0];
    // d_in[1] (swap_pattern int32[130]) is the fixed 65<->65 half swap; computed
    // analytically, so it isn't gathered.
    float* out = (float*)d_out;

    int n_frames = in_sizes[0] / FRAME_LEN;
    int n_warps  = (n_frames + 1) / 2;
    const int threads = 256;
    int warps_per_block = threads / 32;
    int blocks = (n_warps + warps_per_block - 1) / warps_per_block;

    hand_sorter_final<<<blocks, threads>>>(X, out, n_frames);
}

// round 16
// speedup vs baseline: 1.0007x; 1.0007x over previous
#include <cuda_runtime.h>

// ============================================================================
// Hand_Input_Sorter — FINAL kernel (converged optimum, session rounds 1-15).
//
// Task: per-frame conditional 65<->65 half-swap of [B*S, 130] fp32, where the
// skip predicate depends on frame elems 0 (h0), 1 (p0), 65 (h1), 66 (p1).
// The swap_pattern input (d_in[1]) is the fixed half-swap permutation and is
// computed analytically rather than gathered.
//
// Measured-optimal configuration (full decision matrix, rounds 1-14):
//   - one-shot grid, 2 adjacent frames per warp, 256-thread blocks
//     (persistent grid-stride: -9%; 512 threads: marginal loss)
//   - front-batched float2 loads (frame base f*130 is even -> 8B aligned),
//     DEFAULT cache policy on loads AND stores (.cs hints measured slower:
//     the 520B-stride frames share straddled 128B-line sectors between
//     neighbor warps, so L2 reuse/write-merge matters)
//   - aligned float2 stores on BOTH paths; the +-65-element swap permutation
//     is realized in registers with warp shuffles (misaligned scattered
//     stores: slower; full float4 alignment via shuffle chains: -13%;
//     smem staging: -32%, ALU-bound)
//   - predicate evaluated lane-locally (h0,p0,h1 already live on lane 0;
//     only p1 shuffled in) with a single boolean broadcast
//
// Measured: device 36.4-37.4us over 5 samples = 272.6 MB / ~36.6us
// ~ 7.45 TB/s effective unique-byte throughput ~ 93% of HBM3e spec.
// Residual vs spec is the irreducible 520B-stride misalignment cost
// (bounded by the R8/R2 falsification experiments).
// ============================================================================

static constexpr int FRAME_LEN = 130;
static constexpr unsigned FULL = 0xFFFFFFFFu;

__device__ __forceinline__ bool compute_skip(float h0, float p0, float h1, float p1)
{
    bool nan0 = isnan(h0);
    bool nan1 = isnan(h1);
    bool skip = (h1 > h0);                 // false if either NaN (IEEE, matches jnp)
    skip |= (nan0 && nan1);                // both missing
    skip |= (nan0 && (h1 == 1.0f));        // only hand1, labeled right
    skip |= (nan1 && (h0 == 0.0f));        // only hand0, labeled left
    if (!nan0 && !nan1 && (h0 == h1)) {
        skip |= ((h0 == 0.0f) && (p0 > p1));
        skip |= ((h0 == 1.0f) && (p0 < p1));
    }
    return skip;
}

// Lane-local predicate + single broadcast: h0=a.x, p0=a.y, h1=b.y are lane 0's
// own registers; p1=b.x@1 is shuffled in. Every lane evaluates compute_skip on
// its local values (garbage off lane 0); only lane 0's result is broadcast.
__device__ __forceinline__ bool frame_skip(float2 a, float2 b)
{
    float p1 = __shfl_sync(FULL, b.x, 1);
    bool local = compute_skip(a.x, a.y, b.y, p1);
    return (bool)__shfl_sync(FULL, (int)local, 0);
}

// Pairs: a = pair[lane] (elems 2l,2l+1), b = pair[lane+32] (elems 64+2l,65+2l),
// c = pair[64] (elems 128,129), loaded uniformly on all lanes.
__device__ __forceinline__ void store_frame(float* __restrict__ o, int lane,
                                            float2 a, float2 b, float2 c, bool skip)
{
    float2* __restrict__ o2 = (float2*)o;
    if (skip) {
        o2[lane]      = a;
        o2[lane + 32] = b;
        if (lane == 0) o2[64] = c;
    } else {
        // out[j] = X[j+65] (j<65) / X[j-65] (j>=65), as float2 slots:
        // slot lane:    {b.y, b[lane+1].x} with b[32] := c
        float bx_next = __shfl_down_sync(FULL, b.x, 1);
        float2 v0 = make_float2(b.y, (lane == 31) ? c.x : bx_next);
        // slot lane+32: lane0 -> {c.y, a[0].x}; else {a[lane-1].y, a.x}
        float ay_prev = __shfl_up_sync(FULL, a.y, 1);
        float a0x     = __shfl_sync(FULL, a.x, 0);
        float2 v1 = (lane == 0) ? make_float2(c.y, a0x)
                                : make_float2(ay_prev, a.x);
        // slot 64: {a[31].y, b[0].x}
        float ay31 = __shfl_sync(FULL, a.y, 31);
        float b0x  = __shfl_sync(FULL, b.x, 0);
        o2[lane]      = v0;
        o2[lane + 32] = v1;
        if (lane == 0) o2[64] = make_float2(ay31, b0x);
    }
}

__global__ __launch_bounds__(256) void hand_sorter_final(
    const float* __restrict__ X,
    float* __restrict__ out,
    int n_frames)
{
    const int gw   = blockIdx.x * (blockDim.x >> 5) + (threadIdx.x >> 5);
    const int lane = threadIdx.x & 31;
    const int f0   = gw * 2;
    if (f0 >= n_frames) return;
    const bool has2 = (f0 + 1) < n_frames;

    const float2* __restrict__ i0 = (const float2*)(X + (size_t)f0 * FRAME_LEN);
    const float2* __restrict__ i1 = (const float2*)(X + (size_t)(f0 + 1) * FRAME_LEN);

    // Front-batch all loads; default cache policy.
    float2 a0 = __ldg(&i0[lane]);
    float2 b0 = __ldg(&i0[lane + 32]);
    float2 c0 = __ldg(&i0[64]);
    float2 a1 = make_float2(0.f, 0.f), b1 = a1, c1 = a1;
    if (has2) {
        a1 = __ldg(&i1[lane]);
        b1 = __ldg(&i1[lane + 32]);
        c1 = __ldg(&i1[64]);
    }

    bool skip0 = frame_skip(a0, b0);
    bool skip1 = has2 ? frame_skip(a1, b1) : false;

    store_frame(out + (size_t)f0 * FRAME_LEN, lane, a0, b0, c0, skip0);
    if (has2)
        store_frame(out + (size_t)(f0 + 1) * FRAME_LEN, lane, a1, b1, c1, skip1);
}

extern "C" void kernel_launch(void* const* d_in, const int* in_sizes, int n_in,
                              void* d_out, int out_size)
{
    const float* X = (const float*)d_in[0];
    // d_in[1] (swap_pattern int32[130]) is the fixed 65<->65 half swap; computed
    // analytically, so it isn't gathered.
    float* out = (float*)d_out;

    int n_frames = in_sizes[0] / FRAME_LEN;
    int n_warps  = (n_frames + 1) / 2;
    const int threads = 256;
    int warps_per_block = threads / 32;
    int blocks = (n_warps + warps_per_block - 1) / warps_per_block;

    hand_sorter_final<<<blocks, threads>>>(X, out, n_frames);
}